// round 3
// baseline (speedup 1.0000x reference)
#include <cuda_runtime.h>
#include <math_constants.h>

#define NTOK 2304      // 48*48
#define CDIM 256
#define BSZ  4
#define NH   8
#define HD   32
#define SCALE 0.17677669529663687f   // 32^-0.5

typedef unsigned long long u64;
__device__ __forceinline__ u64 pk2(float lo, float hi) {
    u64 r; asm("mov.b64 %0,{%1,%2};" : "=l"(r) : "f"(lo), "f"(hi)); return r;
}
__device__ __forceinline__ void upk2(u64 v, float& lo, float& hi) {
    asm("mov.b64 {%0,%1},%2;" : "=f"(lo), "=f"(hi) : "l"(v));
}
__device__ __forceinline__ void fma2(u64& d, u64 a, u64 b) {
    asm("fma.rn.f32x2 %0,%1,%2,%0;" : "+l"(d) : "l"(a), "l"(b));
}
__device__ __forceinline__ void mul2(u64& d, u64 a) {
    asm("mul.rn.f32x2 %0,%0,%1;" : "+l"(d) : "l"(a));
}

// ---------------- scratch ----------------
__device__ float g_Q [2][BSZ*NH*NTOK*HD];   // (b,h,n,d)
__device__ float g_Kt[2][BSZ*NH*HD*NTOK];   // (b,h,d,n)
__device__ float g_V [2][BSZ*NH*NTOK*HD];   // (b,h,n,d)
__device__ float g_AttO[2][BSZ*NTOK*CDIM];  // (b,n,c)

// ---------------- fused QKV projection: all 4 GEMMs in one launch ----------------
// blockIdx.z = seg*4 + b; seg: 0=Qimg 1=KVradar 2=Qradar 3=KVimg
// out[n,c'] = sum_c X[b,c,n] * W[c,c']
__global__ void __launch_bounds__(256) proj_qkv_fused(
    const float* __restrict__ img, const float* __restrict__ radar,
    const float* __restrict__ Wq_img, const float* __restrict__ Wkv_radar,
    const float* __restrict__ Wq_radar, const float* __restrict__ Wkv_img)
{
    const int zz  = blockIdx.z;
    const int seg = zz >> 2;
    const int b   = zz & 3;
    const float* X; const float* W; int ncol, kind, attn;
    switch (seg) {
        case 0:  X = img;   W = Wq_img;    ncol = CDIM;     kind = 0; attn = 0; break;
        case 1:  X = radar; W = Wkv_radar; ncol = 2 * CDIM; kind = 1; attn = 0; break;
        case 2:  X = radar; W = Wq_radar;  ncol = CDIM;     kind = 0; attn = 1; break;
        default: X = img;   W = Wkv_img;   ncol = 2 * CDIM; kind = 1; attn = 1; break;
    }
    const int n0 = blockIdx.y * 64;
    if (n0 >= ncol) return;
    const int m0 = blockIdx.x * 64;

    __shared__ __align__(16) float  As[16][64];
    __shared__ __align__(16) float2 Bsd[16][64];   // duplicated pairs

    const int tx = threadIdx.x & 15, ty = threadIdx.x >> 4;
    const int tid = threadIdx.x;
    const float* Xb = X + (size_t)b * CDIM * NTOK;

    u64 acc2[2][4] = {};
    for (int k0 = 0; k0 < CDIM; k0 += 16) {
        #pragma unroll
        for (int i = tid; i < 16 * 64; i += 256) {
            int k = i >> 6, m = i & 63;
            As[k][m] = Xb[(size_t)(k0 + k) * NTOK + m0 + m];
        }
        #pragma unroll
        for (int i = tid; i < 16 * 64; i += 256) {
            int k = i >> 6, n = i & 63;
            float w = W[(size_t)(k0 + k) * ncol + n0 + n];
            Bsd[k][n] = make_float2(w, w);
        }
        __syncthreads();
        #pragma unroll
        for (int k = 0; k < 16; k++) {
            ulonglong2 a   = *(const ulonglong2*)&As[k][ty * 4];
            ulonglong2 b01 = *(const ulonglong2*)&Bsd[k][tx * 4];
            ulonglong2 b23 = *(const ulonglong2*)&Bsd[k][tx * 4 + 2];
            fma2(acc2[0][0], a.x, b01.x); fma2(acc2[1][0], a.y, b01.x);
            fma2(acc2[0][1], a.x, b01.y); fma2(acc2[1][1], a.y, b01.y);
            fma2(acc2[0][2], a.x, b23.x); fma2(acc2[1][2], a.y, b23.x);
            fma2(acc2[0][3], a.x, b23.y); fma2(acc2[1][3], a.y, b23.y);
        }
        __syncthreads();
    }

    float acc[4][4];
    #pragma unroll
    for (int p = 0; p < 2; p++)
        #pragma unroll
        for (int j = 0; j < 4; j++)
            upk2(acc2[p][j], acc[2*p][j], acc[2*p+1][j]);

    float* oQ  = g_Q[attn];
    float* oKt = g_Kt[attn];
    float* oV  = g_V[attn];
    #pragma unroll
    for (int i = 0; i < 4; i++) {
        int n = m0 + ty * 4 + i;
        #pragma unroll
        for (int j = 0; j < 4; j++) {
            int cp = n0 + tx * 4 + j;
            float v = acc[i][j];
            if (kind == 0) {
                int h = cp >> 5, d = cp & 31;
                oQ[(((size_t)b * NH + h) * NTOK + n) * HD + d] = v;
            } else {
                if (cp < CDIM) {
                    int h = cp >> 5, d = cp & 31;
                    oKt[(((size_t)b * NH + h) * HD + d) * NTOK + n] = v;
                } else {
                    int c2 = cp - CDIM;
                    int h = c2 >> 5, d = c2 & 31;
                    oV[(((size_t)b * NH + h) * NTOK + n) * HD + d] = v;
                }
            }
        }
    }
}

// ---------------- attention: register-tiled flash, FFMA2, dup-stored K/V ----------------
// grid: (NTOK/64, BSZ*NH, 2). block 256 = 16x16.
__global__ void __launch_bounds__(256) attn_kernel(const float* __restrict__ umask)
{
    const int attn = blockIdx.z;
    const int bh   = blockIdx.y;
    const int b    = bh >> 3;
    const int h    = bh & 7;
    const int row0 = blockIdx.x * 64;

    const float* Q  = g_Q[attn];
    const float* Kt = g_Kt[attn];
    const float* V  = g_V[attn];

    __shared__ __align__(16) float  Qs[HD][68];    // [d][m] pre-scaled
    __shared__ __align__(16) float2 Ksd[HD][64];   // [d][j] dup pairs
    __shared__ __align__(16) float2 Vsd[64][HD];   // [j][d] dup pairs
    __shared__ __align__(16) float  Ps[64][68];    // [j][m]
    __shared__ float tws[64];

    const int tid = threadIdx.x;
    const int tx  = tid & 15;
    const int ty  = tid >> 4;

    if (tid < 64) {
        int n = row0 + tid;
        float f = SCALE;
        if (attn == 0) f *= 1.0f / (umask[(size_t)b * NTOK + n] + 1e-6f);
        tws[tid] = f;
    }
    __syncthreads();

    #pragma unroll
    for (int i = tid; i < 64 * HD; i += 256) {
        int m = i >> 5, d = i & 31;
        Qs[d][m] = Q[((size_t)bh * NTOK + row0 + m) * HD + d] * tws[m];
    }

    const size_t ktbase = (size_t)bh * HD * NTOK;
    const size_t vbase  = (size_t)bh * NTOK * HD;

    float runm[4], denom[4];
    #pragma unroll
    for (int i = 0; i < 4; i++) { runm[i] = -CUDART_INF_F; denom[i] = 0.f; }
    u64 oacc[2][2] = {};

    for (int kb = 0; kb < NTOK; kb += 64) {
        __syncthreads();
        #pragma unroll
        for (int i = tid; i < HD * 64; i += 256) {
            int d = i >> 6, j = i & 63;
            float v = Kt[ktbase + (size_t)d * NTOK + kb + j];
            Ksd[d][j] = make_float2(v, v);
        }
        #pragma unroll
        for (int i = tid; i < 64 * HD; i += 256) {
            int j = i >> 5, d = i & 31;
            float v = V[vbase + (size_t)(kb + j) * HD + d];
            Vsd[j][d] = make_float2(v, v);
        }
        __syncthreads();

        // ---- S = Qs^T K : 4 rows x 4 keys, row-pair packed ----
        u64 sacc[2][4] = {};
        #pragma unroll
        for (int d = 0; d < HD; d++) {
            ulonglong2 av  = *(const ulonglong2*)&Qs[d][ty * 4];
            ulonglong2 b01 = *(const ulonglong2*)&Ksd[d][tx * 4];
            ulonglong2 b23 = *(const ulonglong2*)&Ksd[d][tx * 4 + 2];
            fma2(sacc[0][0], av.x, b01.x); fma2(sacc[1][0], av.y, b01.x);
            fma2(sacc[0][1], av.x, b01.y); fma2(sacc[1][1], av.y, b01.y);
            fma2(sacc[0][2], av.x, b23.x); fma2(sacc[1][2], av.y, b23.x);
            fma2(sacc[0][3], av.x, b23.y); fma2(sacc[1][3], av.y, b23.y);
        }

        float s[4][4];
        #pragma unroll
        for (int p = 0; p < 2; p++)
            #pragma unroll
            for (int j = 0; j < 4; j++)
                upk2(sacc[p][j], s[2*p][j], s[2*p+1][j]);

        // ---- online softmax (row reduce over 16 tx lanes) ----
        float corrv[4];
        #pragma unroll
        for (int i = 0; i < 4; i++) {
            float mloc = fmaxf(fmaxf(s[i][0], s[i][1]), fmaxf(s[i][2], s[i][3]));
            #pragma unroll
            for (int o = 8; o > 0; o >>= 1)
                mloc = fmaxf(mloc, __shfl_xor_sync(0xffffffffu, mloc, o));
            float nm = fmaxf(runm[i], mloc);
            float corr = __expf(runm[i] - nm);
            float psum = 0.f;
            #pragma unroll
            for (int j = 0; j < 4; j++) {
                float pe = __expf(s[i][j] - nm);
                s[i][j] = pe;
                psum += pe;
            }
            #pragma unroll
            for (int o = 8; o > 0; o >>= 1)
                psum += __shfl_xor_sync(0xffffffffu, psum, o);
            denom[i] = denom[i] * corr + psum;
            runm[i] = nm;
            corrv[i] = corr;
        }
        u64 c0 = pk2(corrv[0], corrv[1]);
        u64 c1 = pk2(corrv[2], corrv[3]);
        mul2(oacc[0][0], c0); mul2(oacc[0][1], c0);
        mul2(oacc[1][0], c1); mul2(oacc[1][1], c1);

        #pragma unroll
        for (int jj = 0; jj < 4; jj++)
            *(float4*)&Ps[tx * 4 + jj][ty * 4] =
                make_float4(s[0][jj], s[1][jj], s[2][jj], s[3][jj]);
        __syncthreads();

        // ---- O += P * V : 4 rows x 2 dims ----
        #pragma unroll 16
        for (int j = 0; j < 64; j++) {
            ulonglong2 pv = *(const ulonglong2*)&Ps[j][ty * 4];
            ulonglong2 vv = *(const ulonglong2*)&Vsd[j][tx * 2];
            fma2(oacc[0][0], pv.x, vv.x); fma2(oacc[1][0], pv.y, vv.x);
            fma2(oacc[0][1], pv.x, vv.y); fma2(oacc[1][1], pv.y, vv.y);
        }
    }

    float o[4][2];
    #pragma unroll
    for (int p = 0; p < 2; p++)
        #pragma unroll
        for (int dd = 0; dd < 2; dd++)
            upk2(oacc[p][dd], o[2*p][dd], o[2*p+1][dd]);

    #pragma unroll
    for (int i = 0; i < 4; i++) {
        float rinv = 1.0f / denom[i];
        int n = row0 + ty * 4 + i;
        #pragma unroll
        for (int dd = 0; dd < 2; dd++)
            g_AttO[attn][((size_t)b * NTOK + n) * CDIM + h * HD + tx * 2 + dd] =
                o[i][dd] * rinv;
    }
}

// ---------------- fused output projection: both modalities in one launch ----------------
// blockIdx.z = which*4 + b
__global__ void __launch_bounds__(256) proj_out_fused(
    const float* __restrict__ Wp_img, const float* __restrict__ bp_img,
    const float* __restrict__ Wp_radar, const float* __restrict__ bp_radar,
    float* __restrict__ out)
{
    const int zz = blockIdx.z;
    const int which = zz >> 2;
    const int b     = zz & 3;
    const float* Wp = which ? Wp_radar : Wp_img;
    const float* bp = which ? bp_radar : bp_img;
    float* outw = out + (size_t)which * BSZ * CDIM * NTOK;

    __shared__ __align__(16) float  As[16][68];
    __shared__ __align__(16) float2 Bsd[16][64];
    const int m0 = blockIdx.x * 64;
    const int n0 = blockIdx.y * 64;
    const int tx = threadIdx.x & 15, ty = threadIdx.x >> 4;
    const int tid = threadIdx.x;
    const float* A = g_AttO[which] + (size_t)b * NTOK * CDIM;

    u64 acc2[2][4] = {};
    for (int k0 = 0; k0 < CDIM; k0 += 16) {
        #pragma unroll
        for (int i = tid; i < 16 * 64; i += 256) {
            int m = i >> 4, k = i & 15;
            As[k][m] = A[(size_t)(m0 + m) * CDIM + k0 + k];
        }
        #pragma unroll
        for (int i = tid; i < 16 * 64; i += 256) {
            int k = i >> 6, n = i & 63;
            float w = Wp[(size_t)(k0 + k) * CDIM + n0 + n];
            Bsd[k][n] = make_float2(w, w);
        }
        __syncthreads();
        #pragma unroll
        for (int k = 0; k < 16; k++) {
            ulonglong2 a   = *(const ulonglong2*)&As[k][ty * 4];
            ulonglong2 b01 = *(const ulonglong2*)&Bsd[k][tx * 4];
            ulonglong2 b23 = *(const ulonglong2*)&Bsd[k][tx * 4 + 2];
            fma2(acc2[0][0], a.x, b01.x); fma2(acc2[1][0], a.y, b01.x);
            fma2(acc2[0][1], a.x, b01.y); fma2(acc2[1][1], a.y, b01.y);
            fma2(acc2[0][2], a.x, b23.x); fma2(acc2[1][2], a.y, b23.x);
            fma2(acc2[0][3], a.x, b23.y); fma2(acc2[1][3], a.y, b23.y);
        }
        __syncthreads();
    }

    float acc[4][4];
    #pragma unroll
    for (int p = 0; p < 2; p++)
        #pragma unroll
        for (int j = 0; j < 4; j++)
            upk2(acc2[p][j], acc[2*p][j], acc[2*p+1][j]);

    float* outb = outw + (size_t)b * CDIM * NTOK;
    #pragma unroll
    for (int j = 0; j < 4; j++) {
        int cp = n0 + tx * 4 + j;
        float bias = bp[cp];
        #pragma unroll
        for (int i = 0; i < 4; i++) {
            int n = m0 + ty * 4 + i;
            outb[(size_t)cp * NTOK + n] = acc[i][j] + bias;
        }
    }
}

// ---------------- launch ----------------
extern "C" void kernel_launch(void* const* d_in, const int* in_sizes, int n_in,
                              void* d_out, int out_size)
{
    const float* img   = (const float*)d_in[0];
    const float* radar = (const float*)d_in[1];
    const float* umask = (const float*)d_in[2];
    const float* Wq_img    = (const float*)d_in[3];
    const float* Wkv_radar = (const float*)d_in[4];
    const float* Wq_radar  = (const float*)d_in[5];
    const float* Wkv_img   = (const float*)d_in[6];
    const float* Wp_img    = (const float*)d_in[7];
    const float* bp_img    = (const float*)d_in[8];
    const float* Wp_radar  = (const float*)d_in[9];
    const float* bp_radar  = (const float*)d_in[10];
    float* out = (float*)d_out;

    dim3 gP(NTOK / 64, 8, 16);     // x: token tiles, y: col tiles (Q segs use 4), z: seg*4+b
    proj_qkv_fused<<<gP, 256>>>(img, radar, Wq_img, Wkv_radar, Wq_radar, Wkv_img);

    dim3 gA(NTOK / 64, BSZ * NH, 2);
    attn_kernel<<<gA, 256>>>(umask);

    dim3 gO(NTOK / 64, CDIM / 64, 8);   // z = which*4 + b
    proj_out_fused<<<gO, 256>>>(Wp_img, bp_img, Wp_radar, bp_radar, out);
}

// round 7
// speedup vs baseline: 1.4666x; 1.4666x over previous
#include <cuda_runtime.h>
#include <math_constants.h>

#define NTOK 2304      // 48*48
#define CDIM 256
#define BSZ  4
#define NH   8
#define HD   32
#define SCALE 0.17677669529663687f   // 32^-0.5

typedef unsigned long long u64;
__device__ __forceinline__ u64 pk2(float lo, float hi) {
    u64 r; asm("mov.b64 %0,{%1,%2};" : "=l"(r) : "f"(lo), "f"(hi)); return r;
}
__device__ __forceinline__ void upk2(u64 v, float& lo, float& hi) {
    asm("mov.b64 {%0,%1},%2;" : "=f"(lo), "=f"(hi) : "l"(v));
}
__device__ __forceinline__ void fma2(u64& d, u64 a, u64 b) {
    asm("fma.rn.f32x2 %0,%1,%2,%0;" : "+l"(d) : "l"(a), "l"(b));
}
__device__ __forceinline__ void mul2(u64& d, u64 a) {
    asm("mul.rn.f32x2 %0,%0,%1;" : "+l"(d) : "l"(a));
}

// ---------------- scratch ----------------
__device__ float g_Q [2][BSZ*NH*NTOK*HD];   // (b,h,n,d)
__device__ float g_Kt[2][BSZ*NH*HD*NTOK];   // (b,h,d,n)
__device__ float g_V [2][BSZ*NH*NTOK*HD];   // (b,h,n,d)
__device__ float g_AttO[2][BSZ*NTOK*CDIM];  // (b,n,c)

// ---------------- fused QKV projection (4 GEMMs, one launch) ----------------
// dup'd operand = A (ty-indexed, broadcast); B native float4 (tx-indexed).
__global__ void __launch_bounds__(256) proj_qkv_fused(
    const float* __restrict__ img, const float* __restrict__ radar,
    const float* __restrict__ Wq_img, const float* __restrict__ Wkv_radar,
    const float* __restrict__ Wq_radar, const float* __restrict__ Wkv_img)
{
    const int zz  = blockIdx.z;
    const int seg = zz >> 2;
    const int b   = zz & 3;
    const float* X; const float* W; int ncol, kind, attn;
    switch (seg) {
        case 0:  X = img;   W = Wq_img;    ncol = CDIM;     kind = 0; attn = 0; break;
        case 1:  X = radar; W = Wkv_radar; ncol = 2 * CDIM; kind = 1; attn = 0; break;
        case 2:  X = radar; W = Wq_radar;  ncol = CDIM;     kind = 0; attn = 1; break;
        default: X = img;   W = Wkv_img;   ncol = 2 * CDIM; kind = 1; attn = 1; break;
    }
    const int n0 = blockIdx.y * 64;
    if (n0 >= ncol) return;
    const int m0 = blockIdx.x * 64;

    __shared__ __align__(16) float2 Asd[16][64];   // dup rows (ty-indexed); 512B rows, aligned
    __shared__ __align__(16) float  Bs [16][64];   // native cols (tx-indexed)

    const int tid = threadIdx.x;
    const int tx = tid & 15, ty = tid >> 4;
    const float* Xb = X + (size_t)b * CDIM * NTOK;

    u64 acc2[4][2] = {};   // [row][colpair]
    for (int k0 = 0; k0 < CDIM; k0 += 16) {
        #pragma unroll
        for (int i = tid; i < 16 * 64; i += 256) {
            int k = i >> 6, m = i & 63;
            float v = Xb[(size_t)(k0 + k) * NTOK + m0 + m];
            Asd[k][m] = make_float2(v, v);
        }
        #pragma unroll
        for (int i = tid; i < 16 * 64; i += 256) {
            int k = i >> 6, n = i & 63;
            Bs[k][n] = W[(size_t)(k0 + k) * ncol + n0 + n];
        }
        __syncthreads();
        #pragma unroll
        for (int k = 0; k < 16; k++) {
            ulonglong2 a01 = *(const ulonglong2*)&Asd[k][ty * 4];     // dup rows 0,1
            ulonglong2 a23 = *(const ulonglong2*)&Asd[k][ty * 4 + 2]; // dup rows 2,3
            ulonglong2 bb  = *(const ulonglong2*)&Bs[k][tx * 4];      // native {n0,n1},{n2,n3}
            fma2(acc2[0][0], a01.x, bb.x); fma2(acc2[0][1], a01.x, bb.y);
            fma2(acc2[1][0], a01.y, bb.x); fma2(acc2[1][1], a01.y, bb.y);
            fma2(acc2[2][0], a23.x, bb.x); fma2(acc2[2][1], a23.x, bb.y);
            fma2(acc2[3][0], a23.y, bb.x); fma2(acc2[3][1], a23.y, bb.y);
        }
        __syncthreads();
    }

    float acc[4][4];
    #pragma unroll
    for (int i = 0; i < 4; i++)
        #pragma unroll
        for (int p = 0; p < 2; p++)
            upk2(acc2[i][p], acc[i][2*p], acc[i][2*p+1]);

    float* oQ  = g_Q[attn];
    float* oKt = g_Kt[attn];
    float* oV  = g_V[attn];
    #pragma unroll
    for (int i = 0; i < 4; i++) {
        int n = m0 + ty * 4 + i;
        #pragma unroll
        for (int j = 0; j < 4; j++) {
            int cp = n0 + tx * 4 + j;
            float v = acc[i][j];
            if (kind == 0) {
                int h = cp >> 5, d = cp & 31;
                oQ[(((size_t)b * NH + h) * NTOK + n) * HD + d] = v;
            } else {
                if (cp < CDIM) {
                    int h = cp >> 5, d = cp & 31;
                    oKt[(((size_t)b * NH + h) * HD + d) * NTOK + n] = v;
                } else {
                    int c2 = cp - CDIM;
                    int h = c2 >> 5, d = c2 & 31;
                    oV[(((size_t)b * NH + h) * NTOK + n) * HD + d] = v;
                }
            }
        }
    }
}

// ---------------- attention: flash, FFMA2, dup-Q / dup-V ----------------
// grid (NTOK/64, BSZ*NH, 2), block 256 = 16x16.
__global__ void __launch_bounds__(256) attn_kernel(const float* __restrict__ umask)
{
    const int attn = blockIdx.z;
    const int bh   = blockIdx.y;
    const int b    = bh >> 3;
    const int h    = bh & 7;
    const int row0 = blockIdx.x * 64;

    const float* Q  = g_Q[attn];
    const float* Kt = g_Kt[attn];
    const float* V  = g_V[attn];

    __shared__ __align__(16) float2 Qsd[HD][66];   // 528B rows (16B-aligned), dup pre-scaled
    __shared__ __align__(16) float  Ks [HD][64];   // [d][j] native
    __shared__ __align__(16) float2 Vsd[64][HD];   // [j][d] dup (tx-contiguous reads)
    __shared__ __align__(16) float  Ps [64][68];   // 272B rows (16B-aligned), native
    __shared__ float tws[64];

    const int tid = threadIdx.x;
    const int tx  = tid & 15;
    const int ty  = tid >> 4;

    if (tid < 64) {
        int n = row0 + tid;
        float f = SCALE;
        if (attn == 0) f *= 1.0f / (umask[(size_t)b * NTOK + n] + 1e-6f);
        tws[tid] = f;
    }
    __syncthreads();

    #pragma unroll
    for (int i = tid; i < 64 * HD; i += 256) {
        int m = i >> 5, d = i & 31;      // d fast: coalesced gmem
        float v = Q[((size_t)bh * NTOK + row0 + m) * HD + d] * tws[m];
        Qsd[d][m] = make_float2(v, v);
    }

    const size_t ktbase = (size_t)bh * HD * NTOK;
    const size_t vbase  = (size_t)bh * NTOK * HD;

    float runm[4], denom[4];
    #pragma unroll
    for (int i = 0; i < 4; i++) { runm[i] = -CUDART_INF_F; denom[i] = 0.f; }
    u64 oacc[2][2] = {};   // [rowpair][d]

    for (int kb = 0; kb < NTOK; kb += 64) {
        __syncthreads();
        #pragma unroll
        for (int i = tid; i < HD * 64; i += 256) {
            int d = i >> 6, j = i & 63;
            Ks[d][j] = Kt[ktbase + (size_t)d * NTOK + kb + j];
        }
        #pragma unroll
        for (int i = tid; i < 64 * HD; i += 256) {
            int j = i >> 5, d = i & 31;
            float v = V[vbase + (size_t)(kb + j) * HD + d];
            Vsd[j][d] = make_float2(v, v);
        }
        __syncthreads();

        // ---- S = Q^T K : 4 rows x (2 native key-pairs) ----
        u64 sacc[4][2] = {};
        #pragma unroll
        for (int d = 0; d < HD; d++) {
            ulonglong2 q01 = *(const ulonglong2*)&Qsd[d][ty * 4];      // dup m0,m1
            ulonglong2 q23 = *(const ulonglong2*)&Qsd[d][ty * 4 + 2];  // dup m2,m3
            ulonglong2 kk  = *(const ulonglong2*)&Ks[d][tx * 4];       // {k0,k1},{k2,k3}
            fma2(sacc[0][0], q01.x, kk.x); fma2(sacc[0][1], q01.x, kk.y);
            fma2(sacc[1][0], q01.y, kk.x); fma2(sacc[1][1], q01.y, kk.y);
            fma2(sacc[2][0], q23.x, kk.x); fma2(sacc[2][1], q23.x, kk.y);
            fma2(sacc[3][0], q23.y, kk.x); fma2(sacc[3][1], q23.y, kk.y);
        }

        float s[4][4];
        #pragma unroll
        for (int i = 0; i < 4; i++)
            #pragma unroll
            for (int p = 0; p < 2; p++)
                upk2(sacc[i][p], s[i][2*p], s[i][2*p+1]);

        // ---- online softmax (row reduce over 16 tx lanes) ----
        float corrv[4];
        #pragma unroll
        for (int i = 0; i < 4; i++) {
            float mloc = fmaxf(fmaxf(s[i][0], s[i][1]), fmaxf(s[i][2], s[i][3]));
            #pragma unroll
            for (int o = 8; o > 0; o >>= 1)
                mloc = fmaxf(mloc, __shfl_xor_sync(0xffffffffu, mloc, o));
            float nm = fmaxf(runm[i], mloc);
            float corr = __expf(runm[i] - nm);
            float psum = 0.f;
            #pragma unroll
            for (int j = 0; j < 4; j++) {
                float pe = __expf(s[i][j] - nm);
                s[i][j] = pe;
                psum += pe;
            }
            #pragma unroll
            for (int o = 8; o > 0; o >>= 1)
                psum += __shfl_xor_sync(0xffffffffu, psum, o);
            denom[i] = denom[i] * corr + psum;
            runm[i] = nm;
            corrv[i] = corr;
        }
        u64 c0 = pk2(corrv[0], corrv[1]);
        u64 c1 = pk2(corrv[2], corrv[3]);
        mul2(oacc[0][0], c0); mul2(oacc[0][1], c0);
        mul2(oacc[1][0], c1); mul2(oacc[1][1], c1);

        #pragma unroll
        for (int jj = 0; jj < 4; jj++)
            *(float4*)&Ps[tx * 4 + jj][ty * 4] =
                make_float4(s[0][jj], s[1][jj], s[2][jj], s[3][jj]);
        __syncthreads();

        // ---- O += P V : native P row-pairs, dup V dims ----
        #pragma unroll 16
        for (int j = 0; j < 64; j++) {
            ulonglong2 pv = *(const ulonglong2*)&Ps[j][ty * 4];    // {P0,P1},{P2,P3}
            ulonglong2 vv = *(const ulonglong2*)&Vsd[j][tx * 2];   // dup d0, dup d1
            fma2(oacc[0][0], pv.x, vv.x); fma2(oacc[1][0], pv.y, vv.x);
            fma2(oacc[0][1], pv.x, vv.y); fma2(oacc[1][1], pv.y, vv.y);
        }
    }

    float o[4][2];
    #pragma unroll
    for (int p = 0; p < 2; p++)
        #pragma unroll
        for (int dd = 0; dd < 2; dd++)
            upk2(oacc[p][dd], o[2*p][dd], o[2*p+1][dd]);

    #pragma unroll
    for (int i = 0; i < 4; i++) {
        float rinv = 1.0f / denom[i];
        int n = row0 + ty * 4 + i;
        #pragma unroll
        for (int dd = 0; dd < 2; dd++)
            g_AttO[attn][((size_t)b * NTOK + n) * CDIM + h * HD + tx * 2 + dd] =
                o[i][dd] * rinv;
    }
}

// ---------------- fused output projection (both modalities) ----------------
__global__ void __launch_bounds__(256) proj_out_fused(
    const float* __restrict__ Wp_img, const float* __restrict__ bp_img,
    const float* __restrict__ Wp_radar, const float* __restrict__ bp_radar,
    float* __restrict__ out)
{
    const int zz = blockIdx.z;
    const int which = zz >> 2;
    const int b     = zz & 3;
    const float* Wp = which ? Wp_radar : Wp_img;
    const float* bp = which ? bp_radar : bp_img;
    float* outw = out + (size_t)which * BSZ * CDIM * NTOK;

    __shared__ __align__(16) float2 Asd[16][66];   // 528B rows (16B-aligned), dup
    __shared__ __align__(16) float  Bs [16][64];
    const int m0 = blockIdx.x * 64;
    const int n0 = blockIdx.y * 64;
    const int tid = threadIdx.x;
    const int tx = tid & 15, ty = tid >> 4;
    const float* A = g_AttO[which] + (size_t)b * NTOK * CDIM;

    u64 acc2[4][2] = {};
    for (int k0 = 0; k0 < CDIM; k0 += 16) {
        #pragma unroll
        for (int i = tid; i < 16 * 64; i += 256) {
            int m = i >> 4, k = i & 15;      // k fast: coalesced gmem
            float v = A[(size_t)(m0 + m) * CDIM + k0 + k];
            Asd[k][m] = make_float2(v, v);
        }
        #pragma unroll
        for (int i = tid; i < 16 * 64; i += 256) {
            int k = i >> 6, n = i & 63;
            Bs[k][n] = Wp[(size_t)(k0 + k) * CDIM + n0 + n];
        }
        __syncthreads();
        #pragma unroll
        for (int k = 0; k < 16; k++) {
            ulonglong2 a01 = *(const ulonglong2*)&Asd[k][ty * 4];
            ulonglong2 a23 = *(const ulonglong2*)&Asd[k][ty * 4 + 2];
            ulonglong2 bb  = *(const ulonglong2*)&Bs[k][tx * 4];
            fma2(acc2[0][0], a01.x, bb.x); fma2(acc2[0][1], a01.x, bb.y);
            fma2(acc2[1][0], a01.y, bb.x); fma2(acc2[1][1], a01.y, bb.y);
            fma2(acc2[2][0], a23.x, bb.x); fma2(acc2[2][1], a23.x, bb.y);
            fma2(acc2[3][0], a23.y, bb.x); fma2(acc2[3][1], a23.y, bb.y);
        }
        __syncthreads();
    }

    float acc[4][4];
    #pragma unroll
    for (int i = 0; i < 4; i++)
        #pragma unroll
        for (int p = 0; p < 2; p++)
            upk2(acc2[i][p], acc[i][2*p], acc[i][2*p+1]);

    float* outb = outw + (size_t)b * CDIM * NTOK;
    #pragma unroll
    for (int j = 0; j < 4; j++) {
        int cp = n0 + tx * 4 + j;
        float bias = bp[cp];
        #pragma unroll
        for (int i = 0; i < 4; i++) {
            int n = m0 + ty * 4 + i;
            outb[(size_t)cp * NTOK + n] = acc[i][j] + bias;
        }
    }
}

// ---------------- launch ----------------
extern "C" void kernel_launch(void* const* d_in, const int* in_sizes, int n_in,
                              void* d_out, int out_size)
{
    const float* img   = (const float*)d_in[0];
    const float* radar = (const float*)d_in[1];
    const float* umask = (const float*)d_in[2];
    const float* Wq_img    = (const float*)d_in[3];
    const float* Wkv_radar = (const float*)d_in[4];
    const float* Wq_radar  = (const float*)d_in[5];
    const float* Wkv_img   = (const float*)d_in[6];
    const float* Wp_img    = (const float*)d_in[7];
    const float* bp_img    = (const float*)d_in[8];
    const float* Wp_radar  = (const float*)d_in[9];
    const float* bp_radar  = (const float*)d_in[10];
    float* out = (float*)d_out;

    dim3 gP(NTOK / 64, 8, 16);
    proj_qkv_fused<<<gP, 256>>>(img, radar, Wq_img, Wkv_radar, Wq_radar, Wkv_img);

    dim3 gA(NTOK / 64, BSZ * NH, 2);
    attn_kernel<<<gA, 256>>>(umask);

    dim3 gO(NTOK / 64, CDIM / 64, 8);
    proj_out_fused<<<gO, 256>>>(Wp_img, bp_img, Wp_radar, bp_radar, out);
}

// round 13
// speedup vs baseline: 1.8540x; 1.2641x over previous
#include <cuda_runtime.h>
#include <math_constants.h>

#define NTOK 2304      // 48*48
#define CDIM 256
#define BSZ  4
#define NH   8
#define HD   32
#define SCALE 0.17677669529663687f   // 32^-0.5

typedef unsigned long long u64;
__device__ __forceinline__ u64 pk2(float lo, float hi) {
    u64 r; asm("mov.b64 %0,{%1,%2};" : "=l"(r) : "f"(lo), "f"(hi)); return r;
}
__device__ __forceinline__ void upk2(u64 v, float& lo, float& hi) {
    asm("mov.b64 {%0,%1},%2;" : "=f"(lo), "=f"(hi) : "l"(v));
}
__device__ __forceinline__ void fma2(u64& d, u64 a, u64 b) {
    asm("fma.rn.f32x2 %0,%1,%2,%0;" : "+l"(d) : "l"(a), "l"(b));
}
__device__ __forceinline__ void mul2(u64& d, u64 a) {
    asm("mul.rn.f32x2 %0,%0,%1;" : "+l"(d) : "l"(a));
}

// ---------------- scratch ----------------
__device__ float g_Q [2][BSZ*NH*NTOK*HD];   // (b,h,n,d)
__device__ float g_Kt[2][BSZ*NH*HD*NTOK];   // (b,h,d,n)
__device__ float g_V [2][BSZ*NH*NTOK*HD];   // (b,h,n,d)
__device__ float g_AttO[2][BSZ*NTOK*CDIM];  // (b,n,c)

// ---------------- fused QKV projection (4 GEMMs, one launch) ----------------
__global__ void __launch_bounds__(256) proj_qkv_fused(
    const float* __restrict__ img, const float* __restrict__ radar,
    const float* __restrict__ Wq_img, const float* __restrict__ Wkv_radar,
    const float* __restrict__ Wq_radar, const float* __restrict__ Wkv_img)
{
    const int zz  = blockIdx.z;
    const int seg = zz >> 2;
    const int b   = zz & 3;
    const float* X; const float* W; int ncol, kind, attn;
    switch (seg) {
        case 0:  X = img;   W = Wq_img;    ncol = CDIM;     kind = 0; attn = 0; break;
        case 1:  X = radar; W = Wkv_radar; ncol = 2 * CDIM; kind = 1; attn = 0; break;
        case 2:  X = radar; W = Wq_radar;  ncol = CDIM;     kind = 0; attn = 1; break;
        default: X = img;   W = Wkv_img;   ncol = 2 * CDIM; kind = 1; attn = 1; break;
    }
    const int n0 = blockIdx.y * 64;
    if (n0 >= ncol) return;
    const int m0 = blockIdx.x * 64;

    __shared__ __align__(16) float2 Asd[16][64];
    __shared__ __align__(16) float  Bs [16][64];

    const int tid = threadIdx.x;
    const int tx = tid & 15, ty = tid >> 4;
    const float* Xb = X + (size_t)b * CDIM * NTOK;

    u64 acc2[4][2] = {};
    for (int k0 = 0; k0 < CDIM; k0 += 16) {
        #pragma unroll
        for (int i = tid; i < 16 * 64; i += 256) {
            int k = i >> 6, m = i & 63;
            float v = Xb[(size_t)(k0 + k) * NTOK + m0 + m];
            Asd[k][m] = make_float2(v, v);
        }
        #pragma unroll
        for (int i = tid; i < 16 * 64; i += 256) {
            int k = i >> 6, n = i & 63;
            Bs[k][n] = W[(size_t)(k0 + k) * ncol + n0 + n];
        }
        __syncthreads();
        #pragma unroll
        for (int k = 0; k < 16; k++) {
            ulonglong2 a01 = *(const ulonglong2*)&Asd[k][ty * 4];
            ulonglong2 a23 = *(const ulonglong2*)&Asd[k][ty * 4 + 2];
            ulonglong2 bb  = *(const ulonglong2*)&Bs[k][tx * 4];
            fma2(acc2[0][0], a01.x, bb.x); fma2(acc2[0][1], a01.x, bb.y);
            fma2(acc2[1][0], a01.y, bb.x); fma2(acc2[1][1], a01.y, bb.y);
            fma2(acc2[2][0], a23.x, bb.x); fma2(acc2[2][1], a23.x, bb.y);
            fma2(acc2[3][0], a23.y, bb.x); fma2(acc2[3][1], a23.y, bb.y);
        }
        __syncthreads();
    }

    float acc[4][4];
    #pragma unroll
    for (int i = 0; i < 4; i++)
        #pragma unroll
        for (int p = 0; p < 2; p++)
            upk2(acc2[i][p], acc[i][2*p], acc[i][2*p+1]);

    float* oQ  = g_Q[attn];
    float* oKt = g_Kt[attn];
    float* oV  = g_V[attn];
    #pragma unroll
    for (int i = 0; i < 4; i++) {
        int n = m0 + ty * 4 + i;
        #pragma unroll
        for (int j = 0; j < 4; j++) {
            int cp = n0 + tx * 4 + j;
            float v = acc[i][j];
            if (kind == 0) {
                int h = cp >> 5, d = cp & 31;
                oQ[(((size_t)b * NH + h) * NTOK + n) * HD + d] = v;
            } else {
                if (cp < CDIM) {
                    int h = cp >> 5, d = cp & 31;
                    oKt[(((size_t)b * NH + h) * HD + d) * NTOK + n] = v;
                } else {
                    int c2 = cp - CDIM;
                    int h = c2 >> 5, d = c2 & 31;
                    oV[(((size_t)b * NH + h) * NTOK + n) * HD + d] = v;
                }
            }
        }
    }
}

// ---------------- attention: R2 layout (native pairs + pk2 packs), float4 staging ----------------
// grid (NTOK/64, BSZ*NH, 2), block 256 = 16x16.
__global__ void __launch_bounds__(256) attn_kernel(const float* __restrict__ umask)
{
    const int attn = blockIdx.z;
    const int bh   = blockIdx.y;
    const int b    = bh >> 3;
    const int h    = bh & 7;
    const int row0 = blockIdx.x * 64;

    const float* Q  = g_Q[attn];
    const float* Kt = g_Kt[attn];
    const float* V  = g_V[attn];

    __shared__ __align__(16) float Qs[HD][68];   // [d][m] pre-scaled (row stride 272B, 16B-mult)
    __shared__ __align__(16) float Ks[HD][68];   // [d][j]
    __shared__ __align__(16) float Vs[64][HD];   // [j][d]
    __shared__ __align__(16) float Ps[64][68];   // [j][m]
    __shared__ float tws[64];

    const int tid = threadIdx.x;
    const int tx  = tid & 15;
    const int ty  = tid >> 4;

    if (tid < 64) {
        int n = row0 + tid;
        float f = SCALE;
        if (attn == 0) f *= 1.0f / (umask[(size_t)b * NTOK + n] + 1e-6f);
        tws[tid] = f;
    }
    __syncthreads();

    #pragma unroll
    for (int i = tid; i < 64 * HD; i += 256) {
        int m = i >> 5, d = i & 31;
        Qs[d][m] = Q[((size_t)bh * NTOK + row0 + m) * HD + d] * tws[m];
    }

    const size_t ktbase = (size_t)bh * HD * NTOK;
    const size_t vbase  = (size_t)bh * NTOK * HD;

    float runm[4], denom[4];
    #pragma unroll
    for (int i = 0; i < 4; i++) { runm[i] = -CUDART_INF_F; denom[i] = 0.f; }
    u64 oacc[2][2] = {};   // [rowpair][d]

    for (int kb = 0; kb < NTOK; kb += 64) {
        __syncthreads();
        // K staging: 32 rows x 64 cols, float4 (2 per thread)
        #pragma unroll
        for (int i = tid; i < 512; i += 256) {
            int d = i >> 4, jq = i & 15;
            *(float4*)&Ks[d][jq * 4] =
                *(const float4*)&Kt[ktbase + (size_t)d * NTOK + kb + jq * 4];
        }
        // V staging: 64 rows x 32 cols, float4 (2 per thread)
        #pragma unroll
        for (int i = tid; i < 512; i += 256) {
            int j = i >> 3, dq = i & 7;
            *(float4*)&Vs[j][dq * 4] =
                *(const float4*)&V[vbase + (size_t)(kb + j) * HD + dq * 4];
        }
        __syncthreads();

        // ---- S = Qs^T Ks : 4x4 microtile, row-pair packed ----
        u64 sacc[2][4] = {};
        #pragma unroll
        for (int d = 0; d < HD; d++) {
            ulonglong2 av = *(const ulonglong2*)&Qs[d][ty * 4];   // native row-pairs
            float4 bk = *(const float4*)&Ks[d][tx * 4];
            u64 b0 = pk2(bk.x, bk.x), b1 = pk2(bk.y, bk.y);
            u64 b2 = pk2(bk.z, bk.z), b3 = pk2(bk.w, bk.w);
            fma2(sacc[0][0], av.x, b0); fma2(sacc[1][0], av.y, b0);
            fma2(sacc[0][1], av.x, b1); fma2(sacc[1][1], av.y, b1);
            fma2(sacc[0][2], av.x, b2); fma2(sacc[1][2], av.y, b2);
            fma2(sacc[0][3], av.x, b3); fma2(sacc[1][3], av.y, b3);
        }

        float s[4][4];
        #pragma unroll
        for (int p = 0; p < 2; p++)
            #pragma unroll
            for (int j = 0; j < 4; j++)
                upk2(sacc[p][j], s[2*p][j], s[2*p+1][j]);

        // ---- online softmax (row reduce over 16 tx lanes) ----
        float corrv[4];
        #pragma unroll
        for (int i = 0; i < 4; i++) {
            float mloc = fmaxf(fmaxf(s[i][0], s[i][1]), fmaxf(s[i][2], s[i][3]));
            #pragma unroll
            for (int o = 8; o > 0; o >>= 1)
                mloc = fmaxf(mloc, __shfl_xor_sync(0xffffffffu, mloc, o));
            float nm = fmaxf(runm[i], mloc);
            float corr = __expf(runm[i] - nm);
            float psum = 0.f;
            #pragma unroll
            for (int j = 0; j < 4; j++) {
                float pe = __expf(s[i][j] - nm);
                s[i][j] = pe;
                psum += pe;
            }
            #pragma unroll
            for (int o = 8; o > 0; o >>= 1)
                psum += __shfl_xor_sync(0xffffffffu, psum, o);
            denom[i] = denom[i] * corr + psum;
            runm[i] = nm;
            corrv[i] = corr;
        }
        u64 c0 = pk2(corrv[0], corrv[1]);
        u64 c1 = pk2(corrv[2], corrv[3]);
        mul2(oacc[0][0], c0); mul2(oacc[0][1], c0);
        mul2(oacc[1][0], c1); mul2(oacc[1][1], c1);

        #pragma unroll
        for (int jj = 0; jj < 4; jj++)
            *(float4*)&Ps[tx * 4 + jj][ty * 4] =
                make_float4(s[0][jj], s[1][jj], s[2][jj], s[3][jj]);
        __syncthreads();

        // ---- O += P * V : 4 rows x 2 dims, row-pair packed ----
        #pragma unroll 16
        for (int j = 0; j < 64; j++) {
            ulonglong2 pv = *(const ulonglong2*)&Ps[j][ty * 4];
            float2 vv = *(const float2*)&Vs[j][tx * 2];
            u64 vb0 = pk2(vv.x, vv.x);
            u64 vb1 = pk2(vv.y, vv.y);
            fma2(oacc[0][0], pv.x, vb0); fma2(oacc[1][0], pv.y, vb0);
            fma2(oacc[0][1], pv.x, vb1); fma2(oacc[1][1], pv.y, vb1);
        }
    }

    float o[4][2];
    #pragma unroll
    for (int p = 0; p < 2; p++)
        #pragma unroll
        for (int dd = 0; dd < 2; dd++)
            upk2(oacc[p][dd], o[2*p][dd], o[2*p+1][dd]);

    #pragma unroll
    for (int i = 0; i < 4; i++) {
        float rinv = 1.0f / denom[i];
        int n = row0 + ty * 4 + i;
        #pragma unroll
        for (int dd = 0; dd < 2; dd++)
            g_AttO[attn][((size_t)b * NTOK + n) * CDIM + h * HD + tx * 2 + dd] =
                o[i][dd] * rinv;
    }
}

// ---------------- fused output projection (both modalities) ----------------
__global__ void __launch_bounds__(256) proj_out_fused(
    const float* __restrict__ Wp_img, const float* __restrict__ bp_img,
    const float* __restrict__ Wp_radar, const float* __restrict__ bp_radar,
    float* __restrict__ out)
{
    const int zz = blockIdx.z;
    const int which = zz >> 2;
    const int b     = zz & 3;
    const float* Wp = which ? Wp_radar : Wp_img;
    const float* bp = which ? bp_radar : bp_img;
    float* outw = out + (size_t)which * BSZ * CDIM * NTOK;

    __shared__ __align__(16) float2 Asd[16][66];
    __shared__ __align__(16) float  Bs [16][64];
    const int m0 = blockIdx.x * 64;
    const int n0 = blockIdx.y * 64;
    const int tid = threadIdx.x;
    const int tx = tid & 15, ty = tid >> 4;
    const float* A = g_AttO[which] + (size_t)b * NTOK * CDIM;

    u64 acc2[4][2] = {};
    for (int k0 = 0; k0 < CDIM; k0 += 16) {
        #pragma unroll
        for (int i = tid; i < 16 * 64; i += 256) {
            int m = i >> 4, k = i & 15;
            float v = A[(size_t)(m0 + m) * CDIM + k0 + k];
            Asd[k][m] = make_float2(v, v);
        }
        #pragma unroll
        for (int i = tid; i < 16 * 64; i += 256) {
            int k = i >> 6, n = i & 63;
            Bs[k][n] = Wp[(size_t)(k0 + k) * CDIM + n0 + n];
        }
        __syncthreads();
        #pragma unroll
        for (int k = 0; k < 16; k++) {
            ulonglong2 a01 = *(const ulonglong2*)&Asd[k][ty * 4];
            ulonglong2 a23 = *(const ulonglong2*)&Asd[k][ty * 4 + 2];
            ulonglong2 bb  = *(const ulonglong2*)&Bs[k][tx * 4];
            fma2(acc2[0][0], a01.x, bb.x); fma2(acc2[0][1], a01.x, bb.y);
            fma2(acc2[1][0], a01.y, bb.x); fma2(acc2[1][1], a01.y, bb.y);
            fma2(acc2[2][0], a23.x, bb.x); fma2(acc2[2][1], a23.x, bb.y);
            fma2(acc2[3][0], a23.y, bb.x); fma2(acc2[3][1], a23.y, bb.y);
        }
        __syncthreads();
    }

    float acc[4][4];
    #pragma unroll
    for (int i = 0; i < 4; i++)
        #pragma unroll
        for (int p = 0; p < 2; p++)
            upk2(acc2[i][p], acc[i][2*p], acc[i][2*p+1]);

    float* outb = outw + (size_t)b * CDIM * NTOK;
    #pragma unroll
    for (int j = 0; j < 4; j++) {
        int cp = n0 + tx * 4 + j;
        float bias = bp[cp];
        #pragma unroll
        for (int i = 0; i < 4; i++) {
            int n = m0 + ty * 4 + i;
            outb[(size_t)cp * NTOK + n] = acc[i][j] + bias;
        }
    }
}

// ---------------- launch ----------------
extern "C" void kernel_launch(void* const* d_in, const int* in_sizes, int n_in,
                              void* d_out, int out_size)
{
    const float* img   = (const float*)d_in[0];
    const float* radar = (const float*)d_in[1];
    const float* umask = (const float*)d_in[2];
    const float* Wq_img    = (const float*)d_in[3];
    const float* Wkv_radar = (const float*)d_in[4];
    const float* Wq_radar  = (const float*)d_in[5];
    const float* Wkv_img   = (const float*)d_in[6];
    const float* Wp_img    = (const float*)d_in[7];
    const float* bp_img    = (const float*)d_in[8];
    const float* Wp_radar  = (const float*)d_in[9];
    const float* bp_radar  = (const float*)d_in[10];
    float* out = (float*)d_out;

    dim3 gP(NTOK / 64, 8, 16);
    proj_qkv_fused<<<gP, 256>>>(img, radar, Wq_img, Wkv_radar, Wq_radar, Wkv_img);

    dim3 gA(NTOK / 64, BSZ * NH, 2);
    attn_kernel<<<gA, 256>>>(umask);

    dim3 gO(NTOK / 64, CDIM / 64, 8);
    proj_out_fused<<<gO, 256>>>(Wp_img, bp_img, Wp_radar, bp_radar, out);
}